// round 5
// baseline (speedup 1.0000x reference)
#include <cuda_runtime.h>
#include <cuda_bf16.h>
#include <math_constants.h>
#include <cstdint>

// Causal attention B=4 L=4096 D=128 fp32 via mma.sync bf16 hi/lo split (3-term).
// Pass 1: convert Q/K/V fp32 -> bf16 hi + bf16 lo (device-global scratch).
// Pass 2: FA2, 256 threads = 8 warps: warp (wq,wk) owns q-rows [16wq,16wq+16) and
// keys [32wk,32wk+32) of each tile. K/V double-buffered via cp.async.
// CTA p handles q-tiles p and 63-p (65 balanced k-tile units per CTA).

namespace {
constexpr int SEQ = 4096, HD = 128, NB = 4;
constexpr int BQ = 64, BK = 64;
constexpr int NQT = SEQ / BQ;  // 64
constexpr int NTH = 256;
constexpr size_t TELEM = (size_t)NB * SEQ * HD;

// smem layout: Q hi/lo 32KB, then 2 K/V buffers of 64KB, then reduce arrays.
constexpr int SM_QH = 0, SM_QL = 16384;
constexpr int SM_BUF0 = 32768;          // per buf: KH+0 KL+16K VH+32K VL+48K
constexpr int BUF_STRIDE = 65536;
constexpr int SM_RED = SM_BUF0 + 2 * BUF_STRIDE;  // 163840: redm[2][64], reds[2][64]
constexpr int SM_OEX = SM_BUF0;         // epilogue O exchange (reuses buffers)
constexpr int OEX_STRIDE = 132;         // floats per row (padded)
constexpr int SMEM_BYTES = SM_RED + 1024;  // 164864
}  // namespace

__device__ __nv_bfloat16 g_hi[3][TELEM];  // 0=K, 1=Q, 2=V
__device__ __nv_bfloat16 g_lo[3][TELEM];

namespace {

__device__ __forceinline__ unsigned smem_u32(const void* p) {
  unsigned a;
  asm("{ .reg .u64 t; cvta.to.shared.u64 t, %1; cvt.u32.u64 %0, t; }" : "=r"(a) : "l"(p));
  return a;
}

__device__ __forceinline__ void splitpk(float x, float y, unsigned& hi, unsigned& lo) {
  __nv_bfloat162 h = __floats2bfloat162_rn(x, y);
  hi = *reinterpret_cast<unsigned*>(&h);
  __nv_bfloat162 l = __floats2bfloat162_rn(x - __bfloat162float(h.x),
                                           y - __bfloat162float(h.y));
  lo = *reinterpret_cast<unsigned*>(&l);
}

__device__ __forceinline__ void ldsm4(unsigned* r, unsigned a) {
  asm volatile("ldmatrix.sync.aligned.m8n8.x4.shared.b16 {%0,%1,%2,%3}, [%4];"
               : "=r"(r[0]), "=r"(r[1]), "=r"(r[2]), "=r"(r[3]) : "r"(a));
}

__device__ __forceinline__ void ldsm4t(unsigned* r, unsigned a) {
  asm volatile("ldmatrix.sync.aligned.m8n8.x4.trans.shared.b16 {%0,%1,%2,%3}, [%4];"
               : "=r"(r[0]), "=r"(r[1]), "=r"(r[2]), "=r"(r[3]) : "r"(a));
}

__device__ __forceinline__ void mma16816(float* d, const unsigned* a, unsigned b0,
                                         unsigned b1) {
  asm volatile(
      "mma.sync.aligned.m16n8k16.row.col.f32.bf16.bf16.f32 "
      "{%0,%1,%2,%3}, {%4,%5,%6,%7}, {%8,%9}, {%0,%1,%2,%3};"
      : "+f"(d[0]), "+f"(d[1]), "+f"(d[2]), "+f"(d[3])
      : "r"(a[0]), "r"(a[1]), "r"(a[2]), "r"(a[3]), "r"(b0), "r"(b1));
}

// Synchronous copy of a 64x128 bf16 tile into swizzled smem (256 threads).
__device__ __forceinline__ void copy_tile(char* sm, int off, const __nv_bfloat16* g,
                                          int tid) {
  const uint4* g4 = (const uint4*)g;
#pragma unroll
  for (int it = 0; it < 4; ++it) {
    const int c16 = it * 256 + tid;
    const int row = c16 >> 4, c = c16 & 15;
    const uint4 v = g4[c16];
    *(uint4*)(sm + off + row * 256 + ((c ^ (row & 7)) << 4)) = v;
  }
}

// Async (cp.async) copy of a 64x128 bf16 tile into swizzled smem (256 threads).
__device__ __forceinline__ void copy_tile_async(unsigned dst, const __nv_bfloat16* g,
                                                int tid) {
  const uint4* g4 = (const uint4*)g;
#pragma unroll
  for (int it = 0; it < 4; ++it) {
    const int c16 = it * 256 + tid;
    const int row = c16 >> 4, c = c16 & 15;
    const unsigned a = dst + row * 256 + ((c ^ (row & 7)) << 4);
    asm volatile("cp.async.cg.shared.global [%0], [%1], 16;" :: "r"(a), "l"(g4 + c16)
                 : "memory");
  }
}
}  // namespace

// ---- Pass 1: fp32 -> bf16 hi/lo ----
__global__ void cvt_kernel(const float* __restrict__ K, const float* __restrict__ Q,
                           const float* __restrict__ V) {
  constexpr int N4 = (int)(TELEM / 4);
  const int stride = gridDim.x * blockDim.x;
  for (int idx = blockIdx.x * blockDim.x + threadIdx.x; idx < 3 * N4; idx += stride) {
    const int t = idx / N4, e = idx - t * N4;
    const float* src = (t == 0) ? K : ((t == 1) ? Q : V);
    const float4 v = ((const float4*)src)[e];
    unsigned h0, l0, h1, l1;
    splitpk(v.x, v.y, h0, l0);
    splitpk(v.z, v.w, h1, l1);
    ((uint2*)g_hi[t])[e] = make_uint2(h0, h1);
    ((uint2*)g_lo[t])[e] = make_uint2(l0, l1);
  }
}

// ---- Pass 2: flash attention ----
__global__ __launch_bounds__(NTH, 1)
void fa_mma_kernel(float* __restrict__ Og) {
  extern __shared__ char sm[];
  const unsigned smb = smem_u32(sm);
  const int tid = threadIdx.x, lane = tid & 31, w = tid >> 5;
  const int wq = w & 3, wk = w >> 2;  // q-row group / key-half
  const int g = lane >> 3, l7 = lane & 7, quad = lane >> 2, qlane = lane & 3;
  const int pair = blockIdx.x, b = blockIdx.y;

  const __nv_bfloat16* Kh = g_hi[0] + (size_t)b * SEQ * HD;
  const __nv_bfloat16* Kl = g_lo[0] + (size_t)b * SEQ * HD;
  const __nv_bfloat16* Qh = g_hi[1] + (size_t)b * SEQ * HD;
  const __nv_bfloat16* Ql = g_lo[1] + (size_t)b * SEQ * HD;
  const __nv_bfloat16* Vh = g_hi[2] + (size_t)b * SEQ * HD;
  const __nv_bfloat16* Vl = g_lo[2] + (size_t)b * SEQ * HD;

  // ldmatrix per-lane row/chunk offsets
  const int rowAl = ((g & 1) << 3) + l7;         // A (Q)
  const int cAoff = g >> 1;
  const int rowBl = (((g >> 1) & 1) << 3) + l7;  // B (K)
  const int cBoff = g & 1;
  const int rowVl = ((g & 1) << 3) + l7;         // V (trans)
  const int cVoff = g >> 1;

  float* redm = (float*)(sm + SM_RED);
  float* reds = (float*)(sm + SM_RED + 512);
  const int er = 16 * wq + quad;  // this thread's even row within the q-tile
  const float scale = 0.088388347648318447f;  // 1/sqrt(128)

  for (int half = 0; half < 2; ++half) {
    const int qt = half ? (NQT - 1 - pair) : pair;
    const int q0 = qt * BQ;

    __syncthreads();  // previous half fully done (Q/epilogue smem reuse)
    copy_tile(sm, SM_QH, Qh + (size_t)q0 * HD, tid);
    copy_tile(sm, SM_QL, Ql + (size_t)q0 * HD, tid);

    // prologue: async-load k-tile 0 into buffer 0
    unsigned buf = 0;
    {
      const unsigned nb = smb + SM_BUF0;
      copy_tile_async(nb, Kh, tid);
      copy_tile_async(nb + 16384u, Kl, tid);
      copy_tile_async(nb + 32768u, Vh, tid);
      copy_tile_async(nb + 49152u, Vl, tid);
      asm volatile("cp.async.commit_group;" ::: "memory");
    }

    float o[16][4];
#pragma unroll
    for (int n = 0; n < 16; ++n)
#pragma unroll
      for (int e = 0; e < 4; ++e) o[n][e] = 0.f;
    float m0 = -CUDART_INF_F, m1 = -CUDART_INF_F, l0 = 0.f, l1 = 0.f;

    for (int kt = 0; kt <= qt; ++kt) {
      asm volatile("cp.async.wait_group 0;" ::: "memory");
      __syncthreads();  // current buffer ready; all prev-iter readers done

      if (kt < qt) {  // issue next tile into the other buffer (overlaps compute)
        const unsigned nb = smb + SM_BUF0 + (buf ^ 1u) * (unsigned)BUF_STRIDE;
        const size_t nk = (size_t)(kt + 1) * BK * HD;
        copy_tile_async(nb, Kh + nk, tid);
        copy_tile_async(nb + 16384u, Kl + nk, tid);
        copy_tile_async(nb + 32768u, Vh + nk, tid);
        copy_tile_async(nb + 49152u, Vl + nk, tid);
        asm volatile("cp.async.commit_group;" ::: "memory");
      }
      const unsigned kb = smb + SM_BUF0 + buf * (unsigned)BUF_STRIDE;
      buf ^= 1u;

      // ---- S = Qh*Kh + Qh*Kl + Ql*Kh  (this warp: keys 32wk..32wk+31) ----
      float s[4][4];
#pragma unroll
      for (int n = 0; n < 4; ++n)
#pragma unroll
        for (int e = 0; e < 4; ++e) s[n][e] = 0.f;

      const unsigned arow = smb + SM_QH + (unsigned)(16 * wq + rowAl) * 256u;
#pragma unroll
      for (int ks = 0; ks < 8; ++ks) {
        unsigned ah[4], al[4];
        const unsigned ca = (unsigned)(((2 * ks + cAoff) ^ l7) << 4);
        ldsm4(ah, arow + ca);
        ldsm4(al, arow + 16384u + ca);
        const unsigned cb = (unsigned)(((2 * ks + cBoff) ^ l7) << 4);
#pragma unroll
        for (int tl = 0; tl < 2; ++tl) {
          const int t = 2 * wk + tl;
          unsigned bh[4], bl[4];
          const unsigned kaddr = kb + (unsigned)(t * 16 + rowBl) * 256u + cb;
          ldsm4(bh, kaddr);
          ldsm4(bl, kaddr + 16384u);
          mma16816(s[2 * tl], ah, bh[0], bh[1]);
          mma16816(s[2 * tl], ah, bl[0], bl[1]);
          mma16816(s[2 * tl], al, bh[0], bh[1]);
          mma16816(s[2 * tl + 1], ah, bh[2], bh[3]);
          mma16816(s[2 * tl + 1], ah, bl[2], bl[3]);
          mma16816(s[2 * tl + 1], al, bh[2], bh[3]);
        }
      }

      // ---- scale + causal mask ----
#pragma unroll
      for (int n = 0; n < 4; ++n)
#pragma unroll
        for (int e = 0; e < 4; ++e) s[n][e] *= scale;
      if (kt == qt) {
#pragma unroll
        for (int n = 0; n < 4; ++n) {
          const int c0 = 32 * wk + 8 * n + 2 * qlane;
          if (c0 > er) s[n][0] = -CUDART_INF_F;
          if (c0 + 1 > er) s[n][1] = -CUDART_INF_F;
          if (c0 > er + 8) s[n][2] = -CUDART_INF_F;
          if (c0 + 1 > er + 8) s[n][3] = -CUDART_INF_F;
        }
      }

      // ---- online softmax: quad-shfl + cross-warp-pair smem exchange ----
      float mx0 = -CUDART_INF_F, mx1 = -CUDART_INF_F;
#pragma unroll
      for (int n = 0; n < 4; ++n) {
        mx0 = fmaxf(mx0, fmaxf(s[n][0], s[n][1]));
        mx1 = fmaxf(mx1, fmaxf(s[n][2], s[n][3]));
      }
      mx0 = fmaxf(mx0, __shfl_xor_sync(0xffffffffu, mx0, 1));
      mx0 = fmaxf(mx0, __shfl_xor_sync(0xffffffffu, mx0, 2));
      mx1 = fmaxf(mx1, __shfl_xor_sync(0xffffffffu, mx1, 1));
      mx1 = fmaxf(mx1, __shfl_xor_sync(0xffffffffu, mx1, 2));
      if (qlane == 0) {
        redm[wk * 64 + er] = mx0;
        redm[wk * 64 + er + 8] = mx1;
      }
      __syncthreads();
      mx0 = fmaxf(mx0, redm[(wk ^ 1) * 64 + er]);
      mx1 = fmaxf(mx1, redm[(wk ^ 1) * 64 + er + 8]);
      const float m0n = fmaxf(m0, mx0), m1n = fmaxf(m1, mx1);
      const float a0 = __expf(m0 - m0n), a1 = __expf(m1 - m1n);
      float s0 = 0.f, s1 = 0.f;
#pragma unroll
      for (int n = 0; n < 4; ++n) {
        s[n][0] = __expf(s[n][0] - m0n);
        s[n][1] = __expf(s[n][1] - m0n);
        s[n][2] = __expf(s[n][2] - m1n);
        s[n][3] = __expf(s[n][3] - m1n);
        s0 += s[n][0] + s[n][1];
        s1 += s[n][2] + s[n][3];
      }
      s0 += __shfl_xor_sync(0xffffffffu, s0, 1);
      s0 += __shfl_xor_sync(0xffffffffu, s0, 2);
      s1 += __shfl_xor_sync(0xffffffffu, s1, 1);
      s1 += __shfl_xor_sync(0xffffffffu, s1, 2);
      if (qlane == 0) {
        reds[wk * 64 + er] = s0;
        reds[wk * 64 + er + 8] = s1;
      }
      __syncthreads();
      s0 += reds[(wk ^ 1) * 64 + er];
      s1 += reds[(wk ^ 1) * 64 + er + 8];
      l0 = l0 * a0 + s0;
      l1 = l1 * a1 + s1;
      m0 = m0n;
      m1 = m1n;

#pragma unroll
      for (int n = 0; n < 16; ++n) {
        o[n][0] *= a0;
        o[n][1] *= a0;
        o[n][2] *= a1;
        o[n][3] *= a1;
      }

      // ---- O += Ph*Vh + Ph*Vl + Pl*Vh  (this warp's 32 keys) ----
#pragma unroll
      for (int ksl = 0; ksl < 2; ++ksl) {
        const int ks = 2 * wk + ksl;
        unsigned ah[4], al[4];
        splitpk(s[2 * ksl][0], s[2 * ksl][1], ah[0], al[0]);
        splitpk(s[2 * ksl][2], s[2 * ksl][3], ah[1], al[1]);
        splitpk(s[2 * ksl + 1][0], s[2 * ksl + 1][1], ah[2], al[2]);
        splitpk(s[2 * ksl + 1][2], s[2 * ksl + 1][3], ah[3], al[3]);
#pragma unroll
        for (int u = 0; u < 8; ++u) {
          unsigned vh[4], vl[4];
          const unsigned vaddr = kb + 32768u + (unsigned)(16 * ks + rowVl) * 256u +
                                 (unsigned)(((2 * u + cVoff) ^ l7) << 4);
          ldsm4t(vh, vaddr);
          ldsm4t(vl, vaddr + 16384u);
          mma16816(o[2 * u], ah, vh[0], vh[1]);
          mma16816(o[2 * u], ah, vl[0], vl[1]);
          mma16816(o[2 * u], al, vh[0], vh[1]);
          mma16816(o[2 * u + 1], ah, vh[2], vh[3]);
          mma16816(o[2 * u + 1], ah, vl[2], vl[3]);
          mma16816(o[2 * u + 1], al, vh[2], vh[3]);
        }
      }
    }  // kt

    // ---- epilogue: sum the two key-half partial O's, normalize, store ----
    __syncthreads();  // all buffer reads done; safe to reuse buf region as OEX
    float* oex = (float*)(sm + SM_OEX);
    if (wk == 1) {
#pragma unroll
      for (int n = 0; n < 16; ++n) {
        const int col = 8 * n + 2 * qlane;
        *(float2*)(oex + er * OEX_STRIDE + col) = make_float2(o[n][0], o[n][1]);
        *(float2*)(oex + (er + 8) * OEX_STRIDE + col) = make_float2(o[n][2], o[n][3]);
      }
    }
    __syncthreads();
    if (wk == 0) {
      const float i0 = 1.f / l0, i1 = 1.f / l1;
      float* og = Og + ((size_t)b * SEQ + q0 + er) * HD;
#pragma unroll
      for (int n = 0; n < 16; ++n) {
        const int col = 8 * n + 2 * qlane;
        const float2 e0 = *(float2*)(oex + er * OEX_STRIDE + col);
        const float2 e1 = *(float2*)(oex + (er + 8) * OEX_STRIDE + col);
        *(float2*)(og + col) = make_float2((o[n][0] + e0.x) * i0, (o[n][1] + e0.y) * i0);
        *(float2*)(og + 8 * HD + col) =
            make_float2((o[n][2] + e1.x) * i1, (o[n][3] + e1.y) * i1);
      }
    }
  }  // half
}

extern "C" void kernel_launch(void* const* d_in, const int* in_sizes, int n_in,
                              void* d_out, int out_size) {
  const float* K = (const float*)d_in[0];
  const float* Q = (const float*)d_in[1];
  const float* V = (const float*)d_in[2];
  float* O = (float*)d_out;

  cvt_kernel<<<2048, 256>>>(K, Q, V);

  cudaFuncSetAttribute(fa_mma_kernel, cudaFuncAttributeMaxDynamicSharedMemorySize,
                       SMEM_BYTES);
  dim3 grid(NQT / 2, NB);
  fa_mma_kernel<<<grid, NTH, SMEM_BYTES>>>(O);
}

// round 8
// speedup vs baseline: 1.0299x; 1.0299x over previous
#include <cuda_runtime.h>
#include <cuda_bf16.h>
#include <math_constants.h>
#include <cstdint>

// Causal attention B=4 L=4096 D=128 fp32 via mma.sync bf16 hi/lo split (3-term).
// Pass 1: convert Q/K/V fp32 -> bf16 hi + bf16 lo (Q pre-scaled by 1/sqrt(128)).
// Pass 2: FA2 with m16n8k16 HMMA, 128 threads (4 warps), 96KB smem -> 2 CTAs/SM.
// Grid = 256 CTAs (one q-tile x batch each), big-first order for load balance.

namespace {
constexpr int SEQ = 4096, HD = 128, NB = 4;
constexpr int BQ = 64, BK = 64;
constexpr int NQT = SEQ / BQ;  // 64
constexpr int NTH = 128;
constexpr size_t TELEM = (size_t)NB * SEQ * HD;

// smem byte offsets (each tile 64x128 bf16 = 16KB, row stride 256B)
constexpr int SM_QH = 0, SM_QL = 16384, SM_KH = 32768, SM_KL = 49152,
              SM_VH = 65536, SM_VL = 81920, SMEM_BYTES = 98304;
}  // namespace

__device__ __nv_bfloat16 g_hi[3][TELEM];  // 0=K, 1=Q(scaled), 2=V
__device__ __nv_bfloat16 g_lo[3][TELEM];

namespace {

__device__ __forceinline__ unsigned smem_u32(const void* p) {
  unsigned a;
  asm("{ .reg .u64 t; cvta.to.shared.u64 t, %1; cvt.u32.u64 %0, t; }" : "=r"(a) : "l"(p));
  return a;
}

__device__ __forceinline__ void splitpk(float x, float y, unsigned& hi, unsigned& lo) {
  __nv_bfloat162 h = __floats2bfloat162_rn(x, y);
  hi = *reinterpret_cast<unsigned*>(&h);
  __nv_bfloat162 l = __floats2bfloat162_rn(x - __bfloat162float(h.x),
                                           y - __bfloat162float(h.y));
  lo = *reinterpret_cast<unsigned*>(&l);
}

__device__ __forceinline__ void ldsm4(unsigned* r, unsigned a) {
  asm volatile("ldmatrix.sync.aligned.m8n8.x4.shared.b16 {%0,%1,%2,%3}, [%4];"
               : "=r"(r[0]), "=r"(r[1]), "=r"(r[2]), "=r"(r[3]) : "r"(a));
}

__device__ __forceinline__ void ldsm4t(unsigned* r, unsigned a) {
  asm volatile("ldmatrix.sync.aligned.m8n8.x4.trans.shared.b16 {%0,%1,%2,%3}, [%4];"
               : "=r"(r[0]), "=r"(r[1]), "=r"(r[2]), "=r"(r[3]) : "r"(a));
}

__device__ __forceinline__ void mma16816(float* d, const unsigned* a, unsigned b0,
                                         unsigned b1) {
  asm volatile(
      "mma.sync.aligned.m16n8k16.row.col.f32.bf16.bf16.f32 "
      "{%0,%1,%2,%3}, {%4,%5,%6,%7}, {%8,%9}, {%0,%1,%2,%3};"
      : "+f"(d[0]), "+f"(d[1]), "+f"(d[2]), "+f"(d[3])
      : "r"(a[0]), "r"(a[1]), "r"(a[2]), "r"(a[3]), "r"(b0), "r"(b1));
}

// Copy a 64x128 bf16 row-major tile from global into swizzled smem (128 threads).
// Chunk = 16B; smem addr = row*256 + ((chunk ^ (row&7)) << 4).
__device__ __forceinline__ void copy_tile(char* sm, int off, const __nv_bfloat16* g,
                                          int tid) {
  const uint4* g4 = (const uint4*)g;
#pragma unroll
  for (int it = 0; it < 8; ++it) {
    const int c16 = it * 128 + tid;  // 0..1023
    const int row = c16 >> 4, c = c16 & 15;
    const uint4 v = g4[c16];
    *(uint4*)(sm + off + row * 256 + ((c ^ (row & 7)) << 4)) = v;
  }
}
}  // namespace

// ---- Pass 1: fp32 -> bf16 hi/lo (Q scaled by 1/sqrt(HD)) ----
__global__ void cvt_kernel(const float* __restrict__ K, const float* __restrict__ Q,
                           const float* __restrict__ V) {
  constexpr int N4 = (int)(TELEM / 4);
  const int stride = gridDim.x * blockDim.x;
  const float qscale = 0.088388347648318447f;  // 1/sqrt(128)
  for (int idx = blockIdx.x * blockDim.x + threadIdx.x; idx < 3 * N4; idx += stride) {
    const int t = idx / N4, e = idx - t * N4;
    const float* src = (t == 0) ? K : ((t == 1) ? Q : V);
    float4 v = ((const float4*)src)[e];
    if (t == 1) {
      v.x *= qscale; v.y *= qscale; v.z *= qscale; v.w *= qscale;
    }
    unsigned h0, l0, h1, l1;
    splitpk(v.x, v.y, h0, l0);
    splitpk(v.z, v.w, h1, l1);
    ((uint2*)g_hi[t])[e] = make_uint2(h0, h1);
    ((uint2*)g_lo[t])[e] = make_uint2(l0, l1);
  }
}

// ---- Pass 2: flash attention ----
__global__ __launch_bounds__(NTH, 2)
void fa_mma_kernel(float* __restrict__ Og) {
  extern __shared__ char sm[];
  const unsigned smb = smem_u32(sm);
  const int tid = threadIdx.x, lane = tid & 31, w = tid >> 5;
  const int g = lane >> 3, l7 = lane & 7, quad = lane >> 2, qlane = lane & 3;
  const int qt = NQT - 1 - blockIdx.x;  // big CTAs first
  const int b = blockIdx.y;
  const int q0 = qt * BQ;

  const __nv_bfloat16* Kh = g_hi[0] + (size_t)b * SEQ * HD;
  const __nv_bfloat16* Kl = g_lo[0] + (size_t)b * SEQ * HD;
  const __nv_bfloat16* Qh = g_hi[1] + (size_t)b * SEQ * HD;
  const __nv_bfloat16* Ql = g_lo[1] + (size_t)b * SEQ * HD;
  const __nv_bfloat16* Vh = g_hi[2] + (size_t)b * SEQ * HD;
  const __nv_bfloat16* Vl = g_lo[2] + (size_t)b * SEQ * HD;

  // ldmatrix per-lane row/chunk offsets
  const int rowAl = ((g & 1) << 3) + l7;         // A (Q): g1/g3 -> rows+8
  const int cAoff = g >> 1;                      //        g2/g3 -> k+8
  const int rowBl = (((g >> 1) & 1) << 3) + l7;  // B (K): g2/g3 -> rows(n)+8
  const int cBoff = g & 1;                       //        g1/g3 -> k+8
  const int rowVl = ((g & 1) << 3) + l7;         // V(trans): g1/g3 -> keys+8
  const int cVoff = g >> 1;                      //        g2/g3 -> d+8

  copy_tile(sm, SM_QH, Qh + (size_t)q0 * HD, tid);
  copy_tile(sm, SM_QL, Ql + (size_t)q0 * HD, tid);

  float o[16][4];
#pragma unroll
  for (int n = 0; n < 16; ++n)
#pragma unroll
    for (int e = 0; e < 4; ++e) o[n][e] = 0.f;
  float m0 = -CUDART_INF_F, m1 = -CUDART_INF_F, l0 = 0.f, l1 = 0.f;

  for (int kt = 0; kt <= qt; ++kt) {
    __syncthreads();  // previous iteration's readers done (and Q ready, kt=0)
    const int k0 = kt * BK;
    copy_tile(sm, SM_KH, Kh + (size_t)k0 * HD, tid);
    copy_tile(sm, SM_KL, Kl + (size_t)k0 * HD, tid);
    copy_tile(sm, SM_VH, Vh + (size_t)k0 * HD, tid);
    copy_tile(sm, SM_VL, Vl + (size_t)k0 * HD, tid);
    __syncthreads();

    // ---- S = Qh*Kh + Qh*Kl + Ql*Kh (Q pre-scaled) ----
    float s[8][4];
#pragma unroll
    for (int n = 0; n < 8; ++n)
#pragma unroll
      for (int e = 0; e < 4; ++e) s[n][e] = 0.f;

    const unsigned arow = smb + SM_QH + (unsigned)(16 * w + rowAl) * 256u;
#pragma unroll
    for (int ks = 0; ks < 8; ++ks) {
      unsigned ah[4], al[4];
      const unsigned ca = (unsigned)(((2 * ks + cAoff) ^ l7) << 4);
      ldsm4(ah, arow + ca);
      ldsm4(al, arow + 16384u + ca);
      const unsigned cb = (unsigned)(((2 * ks + cBoff) ^ l7) << 4);
#pragma unroll
      for (int t = 0; t < 4; ++t) {
        unsigned bh[4], bl[4];
        const unsigned kaddr = smb + SM_KH + (unsigned)(t * 16 + rowBl) * 256u + cb;
        ldsm4(bh, kaddr);
        ldsm4(bl, kaddr + 16384u);
        mma16816(s[2 * t], ah, bh[0], bh[1]);
        mma16816(s[2 * t], ah, bl[0], bl[1]);
        mma16816(s[2 * t], al, bh[0], bh[1]);
        mma16816(s[2 * t + 1], ah, bh[2], bh[3]);
        mma16816(s[2 * t + 1], ah, bl[2], bl[3]);
        mma16816(s[2 * t + 1], al, bh[2], bh[3]);
      }
    }

    // ---- causal mask (scale already folded into Q) ----
    if (kt == qt) {
      const int r0l = 16 * w + quad;
#pragma unroll
      for (int n = 0; n < 8; ++n) {
        const int c0 = 8 * n + 2 * qlane;
        if (c0 > r0l) s[n][0] = -CUDART_INF_F;
        if (c0 + 1 > r0l) s[n][1] = -CUDART_INF_F;
        if (c0 > r0l + 8) s[n][2] = -CUDART_INF_F;
        if (c0 + 1 > r0l + 8) s[n][3] = -CUDART_INF_F;
      }
    }

    // ---- online softmax (quad = the 4 lanes sharing a row) ----
    float mx0 = -CUDART_INF_F, mx1 = -CUDART_INF_F;
#pragma unroll
    for (int n = 0; n < 8; ++n) {
      mx0 = fmaxf(mx0, fmaxf(s[n][0], s[n][1]));
      mx1 = fmaxf(mx1, fmaxf(s[n][2], s[n][3]));
    }
    mx0 = fmaxf(mx0, __shfl_xor_sync(0xffffffffu, mx0, 1));
    mx0 = fmaxf(mx0, __shfl_xor_sync(0xffffffffu, mx0, 2));
    mx1 = fmaxf(mx1, __shfl_xor_sync(0xffffffffu, mx1, 1));
    mx1 = fmaxf(mx1, __shfl_xor_sync(0xffffffffu, mx1, 2));
    const float m0n = fmaxf(m0, mx0), m1n = fmaxf(m1, mx1);
    const float a0 = __expf(m0 - m0n), a1 = __expf(m1 - m1n);
    float s0 = 0.f, s1 = 0.f;
#pragma unroll
    for (int n = 0; n < 8; ++n) {
      s[n][0] = __expf(s[n][0] - m0n);
      s[n][1] = __expf(s[n][1] - m0n);
      s[n][2] = __expf(s[n][2] - m1n);
      s[n][3] = __expf(s[n][3] - m1n);
      s0 += s[n][0] + s[n][1];
      s1 += s[n][2] + s[n][3];
    }
    s0 += __shfl_xor_sync(0xffffffffu, s0, 1);
    s0 += __shfl_xor_sync(0xffffffffu, s0, 2);
    s1 += __shfl_xor_sync(0xffffffffu, s1, 1);
    s1 += __shfl_xor_sync(0xffffffffu, s1, 2);
    l0 = l0 * a0 + s0;
    l1 = l1 * a1 + s1;
    m0 = m0n;
    m1 = m1n;

#pragma unroll
    for (int n = 0; n < 16; ++n) {
      o[n][0] *= a0;
      o[n][1] *= a0;
      o[n][2] *= a1;
      o[n][3] *= a1;
    }

    // ---- O += Ph*Vh + Ph*Vl + Pl*Vh ----
#pragma unroll
    for (int ks = 0; ks < 4; ++ks) {
      unsigned ah[4], al[4];
      splitpk(s[2 * ks][0], s[2 * ks][1], ah[0], al[0]);
      splitpk(s[2 * ks][2], s[2 * ks][3], ah[1], al[1]);
      splitpk(s[2 * ks + 1][0], s[2 * ks + 1][1], ah[2], al[2]);
      splitpk(s[2 * ks + 1][2], s[2 * ks + 1][3], ah[3], al[3]);
#pragma unroll
      for (int u = 0; u < 8; ++u) {
        unsigned vh[4], vl[4];
        const unsigned vaddr = smb + SM_VH + (unsigned)(16 * ks + rowVl) * 256u +
                               (unsigned)(((2 * u + cVoff) ^ l7) << 4);
        ldsm4t(vh, vaddr);
        ldsm4t(vl, vaddr + 16384u);
        mma16816(o[2 * u], ah, vh[0], vh[1]);
        mma16816(o[2 * u], ah, vl[0], vl[1]);
        mma16816(o[2 * u], al, vh[0], vh[1]);
        mma16816(o[2 * u + 1], ah, vh[2], vh[3]);
        mma16816(o[2 * u + 1], ah, vl[2], vl[3]);
        mma16816(o[2 * u + 1], al, vh[2], vh[3]);
      }
    }
  }  // kt

  // ---- epilogue ----
  const float i0 = 1.f / l0, i1 = 1.f / l1;
  const int r0 = q0 + 16 * w + quad;
  float* og = Og + ((size_t)b * SEQ + r0) * HD;
#pragma unroll
  for (int n = 0; n < 16; ++n) {
    const int col = 8 * n + 2 * qlane;
    *(float2*)(og + col) = make_float2(o[n][0] * i0, o[n][1] * i0);
    *(float2*)(og + 8 * HD + col) = make_float2(o[n][2] * i1, o[n][3] * i1);
  }
}

extern "C" void kernel_launch(void* const* d_in, const int* in_sizes, int n_in,
                              void* d_out, int out_size) {
  const float* K = (const float*)d_in[0];
  const float* Q = (const float*)d_in[1];
  const float* V = (const float*)d_in[2];
  float* O = (float*)d_out;

  cvt_kernel<<<2048, 256>>>(K, Q, V);

  cudaFuncSetAttribute(fa_mma_kernel, cudaFuncAttributeMaxDynamicSharedMemorySize,
                       SMEM_BYTES);
  dim3 grid(NQT, NB);
  fa_mma_kernel<<<grid, NTH, SMEM_BYTES>>>(O);
}

// round 10
// speedup vs baseline: 1.7150x; 1.6653x over previous
#include <cuda_runtime.h>
#include <cuda_bf16.h>
#include <math_constants.h>
#include <cstdint>

// Causal attention B=4 L=4096 D=128 fp32 via mma.sync bf16 hi/lo split (3-term).
// Pass 1: convert Q/K/V fp32 -> bf16 hi + bf16 lo (Q pre-scaled by 1/sqrt(128)).
// Pass 2: FA2 with m16n8k16 HMMA, 128 threads (4 warps). CTA p handles q-tiles
// p and 63-p (65 balanced k-tile units). K/V double-buffered with cp.async so
// the global->smem load phase overlaps the MMA/softmax of the previous tile.

namespace {
constexpr int SEQ = 4096, HD = 128, NB = 4;
constexpr int BQ = 64, BK = 64;
constexpr int NQT = SEQ / BQ;  // 64
constexpr int NTH = 128;
constexpr size_t TELEM = (size_t)NB * SEQ * HD;

// smem: Q hi/lo 32KB, then two 64KB K/V buffers (KH,KL,VH,VL each 16KB).
constexpr int SM_QH = 0, SM_QL = 16384;
constexpr int SM_BUF0 = 32768;
constexpr int BUF_STRIDE = 65536;
constexpr int SMEM_BYTES = SM_BUF0 + 2 * BUF_STRIDE;  // 163840
}  // namespace

__device__ __nv_bfloat16 g_hi[3][TELEM];  // 0=K, 1=Q(scaled), 2=V
__device__ __nv_bfloat16 g_lo[3][TELEM];

namespace {

__device__ __forceinline__ unsigned smem_u32(const void* p) {
  unsigned a;
  asm("{ .reg .u64 t; cvta.to.shared.u64 t, %1; cvt.u32.u64 %0, t; }" : "=r"(a) : "l"(p));
  return a;
}

__device__ __forceinline__ void splitpk(float x, float y, unsigned& hi, unsigned& lo) {
  __nv_bfloat162 h = __floats2bfloat162_rn(x, y);
  hi = *reinterpret_cast<unsigned*>(&h);
  __nv_bfloat162 l = __floats2bfloat162_rn(x - __bfloat162float(h.x),
                                           y - __bfloat162float(h.y));
  lo = *reinterpret_cast<unsigned*>(&l);
}

__device__ __forceinline__ void ldsm4(unsigned* r, unsigned a) {
  asm volatile("ldmatrix.sync.aligned.m8n8.x4.shared.b16 {%0,%1,%2,%3}, [%4];"
               : "=r"(r[0]), "=r"(r[1]), "=r"(r[2]), "=r"(r[3]) : "r"(a));
}

__device__ __forceinline__ void ldsm4t(unsigned* r, unsigned a) {
  asm volatile("ldmatrix.sync.aligned.m8n8.x4.trans.shared.b16 {%0,%1,%2,%3}, [%4];"
               : "=r"(r[0]), "=r"(r[1]), "=r"(r[2]), "=r"(r[3]) : "r"(a));
}

__device__ __forceinline__ void mma16816(float* d, const unsigned* a, unsigned b0,
                                         unsigned b1) {
  asm volatile(
      "mma.sync.aligned.m16n8k16.row.col.f32.bf16.bf16.f32 "
      "{%0,%1,%2,%3}, {%4,%5,%6,%7}, {%8,%9}, {%0,%1,%2,%3};"
      : "+f"(d[0]), "+f"(d[1]), "+f"(d[2]), "+f"(d[3])
      : "r"(a[0]), "r"(a[1]), "r"(a[2]), "r"(a[3]), "r"(b0), "r"(b1));
}

// Synchronous copy of a 64x128 bf16 tile into swizzled smem (128 threads).
// Chunk = 16B; smem addr = row*256 + ((chunk ^ (row&7)) << 4).
__device__ __forceinline__ void copy_tile(char* sm, int off, const __nv_bfloat16* g,
                                          int tid) {
  const uint4* g4 = (const uint4*)g;
#pragma unroll
  for (int it = 0; it < 8; ++it) {
    const int c16 = it * 128 + tid;  // 0..1023
    const int row = c16 >> 4, c = c16 & 15;
    const uint4 v = g4[c16];
    *(uint4*)(sm + off + row * 256 + ((c ^ (row & 7)) << 4)) = v;
  }
}

// Async copy of a 64x128 bf16 tile into swizzled smem (128 threads).
__device__ __forceinline__ void copy_tile_async(unsigned dst, const __nv_bfloat16* g,
                                                int tid) {
  const uint4* g4 = (const uint4*)g;
#pragma unroll
  for (int it = 0; it < 8; ++it) {
    const int c16 = it * 128 + tid;
    const int row = c16 >> 4, c = c16 & 15;
    const unsigned a = dst + row * 256 + ((c ^ (row & 7)) << 4);
    asm volatile("cp.async.cg.shared.global [%0], [%1], 16;" :: "r"(a), "l"(g4 + c16)
                 : "memory");
  }
}
}  // namespace

// ---- Pass 1: fp32 -> bf16 hi/lo (Q scaled by 1/sqrt(HD)) ----
__global__ void cvt_kernel(const float* __restrict__ K, const float* __restrict__ Q,
                           const float* __restrict__ V) {
  constexpr int N4 = (int)(TELEM / 4);
  const int stride = gridDim.x * blockDim.x;
  const float qscale = 0.088388347648318447f;  // 1/sqrt(128)
  for (int idx = blockIdx.x * blockDim.x + threadIdx.x; idx < 3 * N4; idx += stride) {
    const int t = idx / N4, e = idx - t * N4;
    const float* src = (t == 0) ? K : ((t == 1) ? Q : V);
    float4 v = ((const float4*)src)[e];
    if (t == 1) {
      v.x *= qscale; v.y *= qscale; v.z *= qscale; v.w *= qscale;
    }
    unsigned h0, l0, h1, l1;
    splitpk(v.x, v.y, h0, l0);
    splitpk(v.z, v.w, h1, l1);
    ((uint2*)g_hi[t])[e] = make_uint2(h0, h1);
    ((uint2*)g_lo[t])[e] = make_uint2(l0, l1);
  }
}

// ---- Pass 2: flash attention ----
__global__ __launch_bounds__(NTH, 1)
void fa_mma_kernel(float* __restrict__ Og) {
  extern __shared__ char sm[];
  const unsigned smb = smem_u32(sm);
  const int tid = threadIdx.x, lane = tid & 31, w = tid >> 5;
  const int g = lane >> 3, l7 = lane & 7, quad = lane >> 2, qlane = lane & 3;
  const int pair = blockIdx.x, b = blockIdx.y;

  const __nv_bfloat16* Kh = g_hi[0] + (size_t)b * SEQ * HD;
  const __nv_bfloat16* Kl = g_lo[0] + (size_t)b * SEQ * HD;
  const __nv_bfloat16* Qh = g_hi[1] + (size_t)b * SEQ * HD;
  const __nv_bfloat16* Ql = g_lo[1] + (size_t)b * SEQ * HD;
  const __nv_bfloat16* Vh = g_hi[2] + (size_t)b * SEQ * HD;
  const __nv_bfloat16* Vl = g_lo[2] + (size_t)b * SEQ * HD;

  // ldmatrix per-lane row/chunk offsets
  const int rowAl = ((g & 1) << 3) + l7;         // A (Q): g1/g3 -> rows+8
  const int cAoff = g >> 1;                      //        g2/g3 -> k+8
  const int rowBl = (((g >> 1) & 1) << 3) + l7;  // B (K): g2/g3 -> rows(n)+8
  const int cBoff = g & 1;                       //        g1/g3 -> k+8
  const int rowVl = ((g & 1) << 3) + l7;         // V(trans): g1/g3 -> keys+8
  const int cVoff = g >> 1;                      //        g2/g3 -> d+8

  for (int half = 0; half < 2; ++half) {
    const int qt = half ? (NQT - 1 - pair) : pair;
    const int q0 = qt * BQ;

    __syncthreads();  // prior half's readers fully done before smem reuse
    copy_tile(sm, SM_QH, Qh + (size_t)q0 * HD, tid);
    copy_tile(sm, SM_QL, Ql + (size_t)q0 * HD, tid);

    // prologue: async-load k-tile 0 into buffer 0
    unsigned buf = 0;
    {
      const unsigned nb = smb + SM_BUF0;
      copy_tile_async(nb, Kh, tid);
      copy_tile_async(nb + 16384u, Kl, tid);
      copy_tile_async(nb + 32768u, Vh, tid);
      copy_tile_async(nb + 49152u, Vl, tid);
      asm volatile("cp.async.commit_group;" ::: "memory");
    }

    float o[16][4];
#pragma unroll
    for (int n = 0; n < 16; ++n)
#pragma unroll
      for (int e = 0; e < 4; ++e) o[n][e] = 0.f;
    float m0 = -CUDART_INF_F, m1 = -CUDART_INF_F, l0 = 0.f, l1 = 0.f;

    for (int kt = 0; kt <= qt; ++kt) {
      asm volatile("cp.async.wait_group 0;" ::: "memory");
      __syncthreads();  // buffer data visible; all warps past last iter's reads

      if (kt < qt) {  // prefetch next tile into the other buffer (overlaps compute)
        const unsigned nb = smb + SM_BUF0 + (buf ^ 1u) * (unsigned)BUF_STRIDE;
        const size_t nk = (size_t)(kt + 1) * BK * HD;
        copy_tile_async(nb, Kh + nk, tid);
        copy_tile_async(nb + 16384u, Kl + nk, tid);
        copy_tile_async(nb + 32768u, Vh + nk, tid);
        copy_tile_async(nb + 49152u, Vl + nk, tid);
        asm volatile("cp.async.commit_group;" ::: "memory");
      }
      const unsigned kb = smb + SM_BUF0 + buf * (unsigned)BUF_STRIDE;
      buf ^= 1u;

      // ---- S = Qh*Kh + Qh*Kl + Ql*Kh (Q pre-scaled) ----
      float s[8][4];
#pragma unroll
      for (int n = 0; n < 8; ++n)
#pragma unroll
        for (int e = 0; e < 4; ++e) s[n][e] = 0.f;

      const unsigned arow = smb + SM_QH + (unsigned)(16 * w + rowAl) * 256u;
#pragma unroll
      for (int ks = 0; ks < 8; ++ks) {
        unsigned ah[4], al[4];
        const unsigned ca = (unsigned)(((2 * ks + cAoff) ^ l7) << 4);
        ldsm4(ah, arow + ca);
        ldsm4(al, arow + 16384u + ca);
        const unsigned cb = (unsigned)(((2 * ks + cBoff) ^ l7) << 4);
#pragma unroll
        for (int t = 0; t < 4; ++t) {
          unsigned bh[4], bl[4];
          const unsigned kaddr = kb + (unsigned)(t * 16 + rowBl) * 256u + cb;
          ldsm4(bh, kaddr);
          ldsm4(bl, kaddr + 16384u);
          // interleave the two accumulators: distance-2 dependency chains
          mma16816(s[2 * t], ah, bh[0], bh[1]);
          mma16816(s[2 * t + 1], ah, bh[2], bh[3]);
          mma16816(s[2 * t], ah, bl[0], bl[1]);
          mma16816(s[2 * t + 1], ah, bl[2], bl[3]);
          mma16816(s[2 * t], al, bh[0], bh[1]);
          mma16816(s[2 * t + 1], al, bh[2], bh[3]);
        }
      }

      // ---- causal mask (scale folded into Q) ----
      if (kt == qt) {
        const int r0l = 16 * w + quad;
#pragma unroll
        for (int n = 0; n < 8; ++n) {
          const int c0 = 8 * n + 2 * qlane;
          if (c0 > r0l) s[n][0] = -CUDART_INF_F;
          if (c0 + 1 > r0l) s[n][1] = -CUDART_INF_F;
          if (c0 > r0l + 8) s[n][2] = -CUDART_INF_F;
          if (c0 + 1 > r0l + 8) s[n][3] = -CUDART_INF_F;
        }
      }

      // ---- online softmax (quad = the 4 lanes sharing a row) ----
      float mx0 = -CUDART_INF_F, mx1 = -CUDART_INF_F;
#pragma unroll
      for (int n = 0; n < 8; ++n) {
        mx0 = fmaxf(mx0, fmaxf(s[n][0], s[n][1]));
        mx1 = fmaxf(mx1, fmaxf(s[n][2], s[n][3]));
      }
      mx0 = fmaxf(mx0, __shfl_xor_sync(0xffffffffu, mx0, 1));
      mx0 = fmaxf(mx0, __shfl_xor_sync(0xffffffffu, mx0, 2));
      mx1 = fmaxf(mx1, __shfl_xor_sync(0xffffffffu, mx1, 1));
      mx1 = fmaxf(mx1, __shfl_xor_sync(0xffffffffu, mx1, 2));
      const float m0n = fmaxf(m0, mx0), m1n = fmaxf(m1, mx1);
      const float a0 = __expf(m0 - m0n), a1 = __expf(m1 - m1n);
      float s0 = 0.f, s1 = 0.f;
#pragma unroll
      for (int n = 0; n < 8; ++n) {
        s[n][0] = __expf(s[n][0] - m0n);
        s[n][1] = __expf(s[n][1] - m0n);
        s[n][2] = __expf(s[n][2] - m1n);
        s[n][3] = __expf(s[n][3] - m1n);
        s0 += s[n][0] + s[n][1];
        s1 += s[n][2] + s[n][3];
      }
      s0 += __shfl_xor_sync(0xffffffffu, s0, 1);
      s0 += __shfl_xor_sync(0xffffffffu, s0, 2);
      s1 += __shfl_xor_sync(0xffffffffu, s1, 1);
      s1 += __shfl_xor_sync(0xffffffffu, s1, 2);
      l0 = l0 * a0 + s0;
      l1 = l1 * a1 + s1;
      m0 = m0n;
      m1 = m1n;

#pragma unroll
      for (int n = 0; n < 16; ++n) {
        o[n][0] *= a0;
        o[n][1] *= a0;
        o[n][2] *= a1;
        o[n][3] *= a1;
      }

      // ---- O += Ph*Vh + Ph*Vl + Pl*Vh ----
#pragma unroll
      for (int ks = 0; ks < 4; ++ks) {
        unsigned ah[4], al[4];
        splitpk(s[2 * ks][0], s[2 * ks][1], ah[0], al[0]);
        splitpk(s[2 * ks][2], s[2 * ks][3], ah[1], al[1]);
        splitpk(s[2 * ks + 1][0], s[2 * ks + 1][1], ah[2], al[2]);
        splitpk(s[2 * ks + 1][2], s[2 * ks + 1][3], ah[3], al[3]);
#pragma unroll
        for (int u = 0; u < 8; ++u) {
          unsigned vh[4], vl[4];
          const unsigned vaddr = kb + 32768u + (unsigned)(16 * ks + rowVl) * 256u +
                                 (unsigned)(((2 * u + cVoff) ^ l7) << 4);
          ldsm4t(vh, vaddr);
          ldsm4t(vl, vaddr + 16384u);
          mma16816(o[2 * u], ah, vh[0], vh[1]);
          mma16816(o[2 * u + 1], ah, vh[2], vh[3]);
          mma16816(o[2 * u], ah, vl[0], vl[1]);
          mma16816(o[2 * u + 1], ah, vl[2], vl[3]);
          mma16816(o[2 * u], al, vh[0], vh[1]);
          mma16816(o[2 * u + 1], al, vh[2], vh[3]);
        }
      }
    }  // kt

    // ---- epilogue ----
    const float i0 = 1.f / l0, i1 = 1.f / l1;
    const int r0 = q0 + 16 * w + quad;
    float* og = Og + ((size_t)b * SEQ + r0) * HD;
#pragma unroll
    for (int n = 0; n < 16; ++n) {
      const int col = 8 * n + 2 * qlane;
      *(float2*)(og + col) = make_float2(o[n][0] * i0, o[n][1] * i0);
      *(float2*)(og + 8 * HD + col) = make_float2(o[n][2] * i1, o[n][3] * i1);
    }
  }  // half
}

extern "C" void kernel_launch(void* const* d_in, const int* in_sizes, int n_in,
                              void* d_out, int out_size) {
  const float* K = (const float*)d_in[0];
  const float* Q = (const float*)d_in[1];
  const float* V = (const float*)d_in[2];
  float* O = (float*)d_out;

  cvt_kernel<<<2048, 256>>>(K, Q, V);

  cudaFuncSetAttribute(fa_mma_kernel, cudaFuncAttributeMaxDynamicSharedMemorySize,
                       SMEM_BYTES);
  dim3 grid(NQT / 2, NB);
  fa_mma_kernel<<<grid, NTH, SMEM_BYTES>>>(O);
}